// round 17
// baseline (speedup 1.0000x reference)
#include <cuda_runtime.h>
#include <cuda_bf16.h>
#include <cstdint>
#include <cstddef>

#define BB 64
#define TT 2048
#define DD 256
#define VV 256

// ---------------- device scratch (no cudaMalloc allowed) ----------------
__device__ __align__(16) float g_EWx[VV * DD];            // E @ Wx_w^T   [v][e]
__device__ __align__(16) float g_G[VV * DD];              // sigmoid(E @ Wz_w^T) [v][e]
__device__ __align__(16) float g_y[(size_t)BB * TT * DD]; // gated hidden states [b,t,e]
__device__ float g_dummy[32];

typedef unsigned long long ull;

// ---------------- helpers ----------------
// packed fp32x2 FMA: acc = a*b + acc  (full fp32 precision, 2 MACs / instr)
#define FFMA2(acc, a, b) \
    asm("fma.rn.f32x2 %0, %1, %2, %0;" : "+l"(acc) : "l"(a), "l"(b))

__device__ __forceinline__ float f32x2_lohi(ull a) {
    float lo, hi;
    asm("mov.b64 {%0, %1}, %2;" : "=f"(lo), "=f"(hi) : "l"(a));
    return lo + hi;
}

// fast tanh: 1 - 2/(exp(2x)+1); exact limits at +-inf, ~1e-6 rel err
__device__ __forceinline__ float tanh_fast(float x) {
    float e = __expf(2.0f * x);
    return 1.0f - __fdividef(2.0f, e + 1.0f);
}

// ============ dummy kernels: keep the fixed ncu capture index on rnn ============
__global__ void dummy_kernel(int v) {
    g_dummy[threadIdx.x & 31] = (float)v + (float)threadIdx.x;
}

// ================= Kernel 1: tiny projection tables =================
__global__ __launch_bounds__(256) void proj_kernel(
    const float* __restrict__ E,
    const float* __restrict__ Wx,
    const float* __restrict__ Wz)
{
    __shared__ __align__(16) float4 er[DD / 4];
    const int v = blockIdx.x;
    const int e = threadIdx.x;
    if (e < DD / 4) er[e] = ((const float4*)(E + (size_t)v * DD))[e];
    __syncthreads();

    const float4* wx4 = (const float4*)(Wx + (size_t)e * DD);
    const float4* wz4 = (const float4*)(Wz + (size_t)e * DD);
    float ax0 = 0.f, ax1 = 0.f, az0 = 0.f, az1 = 0.f;
#pragma unroll 8
    for (int i = 0; i < DD / 4; i++) {
        float4 ev = er[i];
        float4 a = wx4[i];
        float4 b = wz4[i];
        ax0 += ev.x * a.x + ev.y * a.y;
        ax1 += ev.z * a.z + ev.w * a.w;
        az0 += ev.x * b.x + ev.y * b.y;
        az1 += ev.z * b.z + ev.w * b.w;
    }
    g_EWx[v * DD + e] = ax0 + ax1;
    g_G[v * DD + e]   = 1.f / (1.f + expf(-(az0 + az1)));
}

// ====== Kernel 2: recurrence — SINGLE CTA PER CHAIN, hybrid reg/smem weights ======
// 64 CTAs (1 per chain), 512 threads, NO cluster, NO cross-SM communication.
// Thread t: g = t>>3 owns outputs e in {4g..4g+3}; kb = t&7 owns k-block
// [32kb, 32kb+32). Per output, k-slice split: first 20 k in REGISTERS
// (4 outputs x 10 ull = 80 regs), last 12 k streamed from SMEM each step
// (rows padded to 52 words -> 4-phase conflict-free LDS.128).
// h double-buffered in smem, 32-float chunks at stride 36 (8 chunk bases per
// warp hit 8 distinct bank groups -> 1-phase broadcast loads).
// Reduce: 3 shfl_xor rounds across the 8 kb-lanes of a group; kb==0 lane
// finalizes 4 outputs (tanh + gate) with vectorized float4 gathers/stores.
// ONE __syncthreads per step. No other sync of any kind.
#define WS_ROW 52                     // 48 weight floats + 4 pad
#define H_CHUNK 36                    // 32 + 4 pad
#define H_WORDS (8 * H_CHUNK)         // 288 per parity
#define WS_WORDS (512 * WS_ROW)       // 26624
#define H_OFF WS_WORDS
#define STOK_OFF (WS_WORDS + 2 * H_WORDS)
#define RNN_SMEM_BYTES ((STOK_OFF + TT) * 4)

__global__ void __launch_bounds__(512, 1)
rnn_kernel(const int* __restrict__ tokens, const float* __restrict__ Wh)
{
    extern __shared__ __align__(16) float sm[];
    float* ws   = sm;                 // streamed weights [512][52]
    float* hf   = sm + H_OFF;         // h double buffer [2][288]
    int*   stok = (int*)(sm + STOK_OFF);

    const int tid = threadIdx.x;
    const int g   = tid >> 3;         // output group: e = 4g..4g+3
    const int kb  = tid & 7;          // k-block: k in [32kb, 32kb+32)
    const int b   = blockIdx.x;
    const bool fin = (kb == 0);

    // ---- register weights: 20 k per output (k = 32kb .. 32kb+19) ----
    ull wreg[40];                     // [o][i], 10 ull per output
#pragma unroll
    for (int o = 0; o < 4; o++) {
        const ull* src = (const ull*)(Wh + (size_t)(4 * g + o) * DD + 32 * kb);
#pragma unroll
        for (int i = 0; i < 10; i++) wreg[o * 10 + i] = src[i];
    }

    // ---- streamed weights into smem: 12 k per output (k = 32kb+20 ..+31) ----
    {
        float* row = ws + tid * WS_ROW;
#pragma unroll
        for (int o = 0; o < 4; o++) {
            const float* src = Wh + (size_t)(4 * g + o) * DD + 32 * kb + 20;
#pragma unroll
            for (int j = 0; j < 12; j++) row[o * 12 + j] = src[j];
        }
    }

    for (int i = tid; i < TT; i += 512) stok[i] = tokens[(size_t)b * TT + i];
    for (int i = tid; i < 2 * H_WORDS; i += 512) hf[i] = 0.f;   // h0 = 0
    __syncthreads();

    float* ybase = g_y + (size_t)b * TT * DD;

    // prefetch step-0 gathers (finalize lanes only)
    float4 wxn = {0, 0, 0, 0}, ggn = {0, 0, 0, 0};
    if (fin) {
        const int tk = stok[0];
        wxn = *(const float4*)(g_EWx + tk * DD + 4 * g);
        ggn = *(const float4*)(g_G   + tk * DD + 4 * g);
    }

    int p = 0;
    for (int t = 0; t < TT; t++) {
        const float4 wx = wxn, gg = ggn;
        if (fin && t + 1 < TT) {
            const int tk = stok[t + 1];
            wxn = *(const float4*)(g_EWx + tk * DD + 4 * g);
            ggn = *(const float4*)(g_G   + tk * DD + 4 * g);
        }

        const float* hb = hf + p * H_WORDS + H_CHUNK * kb;

        ull a0 = 0ull, a1 = 0ull, a2 = 0ull, a3 = 0ull;
        // ---- register-weight part: k 0..19 of this block ----
#pragma unroll
        for (int j = 0; j < 5; j++) {
            ulonglong2 hv = *(const ulonglong2*)(hb + 4 * j);
            FFMA2(a0, wreg[0 * 10 + 2 * j], hv.x);
            FFMA2(a0, wreg[0 * 10 + 2 * j + 1], hv.y);
            FFMA2(a1, wreg[1 * 10 + 2 * j], hv.x);
            FFMA2(a1, wreg[1 * 10 + 2 * j + 1], hv.y);
            FFMA2(a2, wreg[2 * 10 + 2 * j], hv.x);
            FFMA2(a2, wreg[2 * 10 + 2 * j + 1], hv.y);
            FFMA2(a3, wreg[3 * 10 + 2 * j], hv.x);
            FFMA2(a3, wreg[3 * 10 + 2 * j + 1], hv.y);
        }
        // ---- smem-weight part: k 20..31 of this block ----
        {
            const float* row = ws + tid * WS_ROW;
#pragma unroll
            for (int j = 0; j < 3; j++) {
                ulonglong2 hv = *(const ulonglong2*)(hb + 20 + 4 * j);
                ulonglong2 w0 = *(const ulonglong2*)(row + 0 * 12 + 4 * j);
                FFMA2(a0, w0.x, hv.x); FFMA2(a0, w0.y, hv.y);
                ulonglong2 w1 = *(const ulonglong2*)(row + 1 * 12 + 4 * j);
                FFMA2(a1, w1.x, hv.x); FFMA2(a1, w1.y, hv.y);
                ulonglong2 w2 = *(const ulonglong2*)(row + 2 * 12 + 4 * j);
                FFMA2(a2, w2.x, hv.x); FFMA2(a2, w2.y, hv.y);
                ulonglong2 w3 = *(const ulonglong2*)(row + 3 * 12 + 4 * j);
                FFMA2(a3, w3.x, hv.x); FFMA2(a3, w3.y, hv.y);
            }
        }

        // ---- reduce across the 8 kb-lanes of this group ----
        float s0 = f32x2_lohi(a0);
        float s1 = f32x2_lohi(a1);
        float s2 = f32x2_lohi(a2);
        float s3 = f32x2_lohi(a3);
#pragma unroll
        for (int r = 1; r < 8; r <<= 1) {
            s0 += __shfl_xor_sync(0xffffffffu, s0, r);
            s1 += __shfl_xor_sync(0xffffffffu, s1, r);
            s2 += __shfl_xor_sync(0xffffffffu, s2, r);
            s3 += __shfl_xor_sync(0xffffffffu, s3, r);
        }

        const int np = p ^ 1;
        if (fin) {
            const float h0 = tanh_fast(s0 + wx.x);
            const float h1 = tanh_fast(s1 + wx.y);
            const float h2 = tanh_fast(s2 + wx.z);
            const float h3 = tanh_fast(s3 + wx.w);
            // padded h store: e = 4g..4g+3 within one 32-chunk
            float4* hd = (float4*)(hf + np * H_WORDS + 4 * g + 4 * (g >> 3));
            *hd = make_float4(h0, h1, h2, h3);
            float4* yd = (float4*)(ybase + (size_t)t * DD + 4 * g);
            *yd = make_float4(h0 * gg.x, h1 * gg.y, h2 * gg.z, h3 * gg.w);
        }

        __syncthreads();
        p = np;
    }
}

// ================= Kernel 3: head GEMM =================
// logits[r][v] = sum_d y[r][d] * E[v][d].
// 64x64 tile per CTA, 4x4 micro-tile per thread, f32x2 pairs along k.
#define HKS 68   // 64 + 4 pad

__global__ __launch_bounds__(256) void head_kernel(
    const float* __restrict__ E,
    float* __restrict__ out)
{
    __shared__ __align__(16) float ys[64 * HKS];
    __shared__ __align__(16) float es[64 * HKS];

    const int tid = threadIdx.x;
    const int tx  = tid & 15;     // v-lane: cols tx, tx+16, tx+32, tx+48
    const int ty  = tid >> 4;     // row group: rows ty*4 .. ty*4+3
    const size_t rowbase = (size_t)(blockIdx.x >> 2) * 64;
    const int vbase = (blockIdx.x & 3) * 64;

    ull acc[4][4];
#pragma unroll
    for (int r = 0; r < 4; r++)
#pragma unroll
        for (int c = 0; c < 4; c++) acc[r][c] = 0ull;

    for (int kc = 0; kc < 4; kc++) {
        const int k0 = kc * 64;
        for (int i = tid; i < 1024; i += 256) {
            const int m = i >> 4, kk = i & 15;
            *(float4*)(ys + m * HKS + kk * 4) =
                *(const float4*)(g_y + (rowbase + m) * DD + k0 + kk * 4);
            *(float4*)(es + m * HKS + kk * 4) =
                *(const float4*)(E + (size_t)(vbase + m) * DD + k0 + kk * 4);
        }
        __syncthreads();

#pragma unroll
        for (int k4 = 0; k4 < 16; k4++) {
            ulonglong2 yv[4], ev[4];
#pragma unroll
            for (int r = 0; r < 4; r++)
                yv[r] = *(const ulonglong2*)(ys + (ty * 4 + r) * HKS + k4 * 4);
#pragma unroll
            for (int c = 0; c < 4; c++)
                ev[c] = *(const ulonglong2*)(es + (tx + 16 * c) * HKS + k4 * 4);
#pragma unroll
            for (int r = 0; r < 4; r++)
#pragma unroll
                for (int c = 0; c < 4; c++) {
                    FFMA2(acc[r][c], yv[r].x, ev[c].x);
                    FFMA2(acc[r][c], yv[r].y, ev[c].y);
                }
        }
        __syncthreads();
    }

#pragma unroll
    for (int r = 0; r < 4; r++) {
        float* orow = out + (rowbase + ty * 4 + r) * VV + vbase;
#pragma unroll
        for (int c = 0; c < 4; c++) {
            orow[tx + 16 * c] = f32x2_lohi(acc[r][c]);
        }
    }
}

// ================= launch =================
extern "C" void kernel_launch(void* const* d_in, const int* in_sizes, int n_in,
                              void* d_out, int out_size)
{
    const int*   tokens = (const int*)  d_in[0];
    const float* E      = (const float*)d_in[1];
    const float* Wx     = (const float*)d_in[2];
    const float* Wh     = (const float*)d_in[3];
    const float* Wz     = (const float*)d_in[4];
    float* out = (float*)d_out;

    cudaFuncSetAttribute(rnn_kernel,
                         cudaFuncAttributeMaxDynamicSharedMemorySize,
                         RNN_SMEM_BYTES);

    // two dummy launches keep the fixed ncu capture index on rnn_kernel
    dummy_kernel<<<1, 32>>>(0);
    dummy_kernel<<<1, 32>>>(1);
    proj_kernel<<<VV, 256>>>(E, Wx, Wz);
    rnn_kernel<<<BB, 512, RNN_SMEM_BYTES>>>(tokens, Wh);
    head_kernel<<<(BB * TT / 64) * (VV / 64), 256>>>(E, out);
}